// round 14
// baseline (speedup 1.0000x reference)
#include <cuda_runtime.h>
#include <cuda_bf16.h>
#include <cstdint>

// Problem constants
#define B_   8
#define N_   256
#define D_   768
#define D2_  1536
#define H_   12
#define HD_  64
#define R_   10
#define EPS_ 1e-5f
#define GSCALE (1.0f / 640.0f)   // SCALE^2 / R

// ---------------- scratch (device globals; no allocation allowed) ----------------
__device__ float g_k [R_ * N_ * D_];          // ref @ Wk        (2560 x 768)
__device__ float g_Gp[H_ * R_ * HD_ * HD_];   // per-(h,r) partial grams
__device__ float g_G [H_ * HD_ * HD_];        // Gbar_h
__device__ float g_qv[B_ * N_ * 2 * D_];      // x @ Wqv         (2048 x 1536)
__device__ float g_pr[B_ * N_ * D_];          // proj output pre-LN

// split-bf16 buffers (hi/lo)
__device__ __nv_bfloat16 g_ah [2048 * 768];   // activations / y
__device__ __nv_bfloat16 g_al [2048 * 768];
__device__ __nv_bfloat16 g_rh [2560 * 768];   // ref split (separate from g_a*)
__device__ __nv_bfloat16 g_rl [2560 * 768];
__device__ __nv_bfloat16 g_wqh[1536 * 768];   // Wqv^T hi  (N,K)
__device__ __nv_bfloat16 g_wql[1536 * 768];
__device__ __nv_bfloat16 g_wkh[ 768 * 768];   // Wk^T
__device__ __nv_bfloat16 g_wkl[ 768 * 768];
__device__ __nv_bfloat16 g_wph[ 768 * 768];   // Wproj^T
__device__ __nv_bfloat16 g_wpl[ 768 * 768];

// ================= low-level helpers (sm_80-era PTX only) =================
__device__ __forceinline__ uint32_t s2u(const void* p) {
    uint32_t a;
    asm("{ .reg .u64 t; cvta.to.shared.u64 t, %1; cvt.u32.u64 %0, t; }" : "=r"(a) : "l"(p));
    return a;
}
__device__ __forceinline__ void cp16(uint32_t sm, const void* gp) {
    asm volatile("cp.async.cg.shared.global [%0], [%1], 16;" :: "r"(sm), "l"(gp));
}
__device__ __forceinline__ void cp_commit() { asm volatile("cp.async.commit_group;"); }
__device__ __forceinline__ void cp_wait0()  { asm volatile("cp.async.wait_group 0;"); }

__device__ __forceinline__ void ldsm4(uint32_t* r, uint32_t a) {
    asm volatile("ldmatrix.sync.aligned.m8n8.x4.shared.b16 {%0,%1,%2,%3}, [%4];"
                 : "=r"(r[0]), "=r"(r[1]), "=r"(r[2]), "=r"(r[3]) : "r"(a));
}
__device__ __forceinline__ void mma16816(float* c, const uint32_t* a, const uint32_t* b) {
    asm volatile("mma.sync.aligned.m16n8k16.row.col.f32.bf16.bf16.f32 "
                 "{%0,%1,%2,%3}, {%4,%5,%6,%7}, {%8,%9}, {%0,%1,%2,%3};"
                 : "+f"(c[0]), "+f"(c[1]), "+f"(c[2]), "+f"(c[3])
                 : "r"(a[0]), "r"(a[1]), "r"(a[2]), "r"(a[3]), "r"(b[0]), "r"(b[1]));
}
__device__ __forceinline__ void split1(float v, __nv_bfloat16& h, __nv_bfloat16& l) {
    h = __float2bfloat16(v);
    l = __float2bfloat16(v - __bfloat162float(h));
}

// ================= split kernels =================
__global__ __launch_bounds__(256) void split_k(const float* __restrict__ X,
                                               __nv_bfloat16* __restrict__ hi,
                                               __nv_bfloat16* __restrict__ lo)
{
    size_t i = ((size_t)blockIdx.x * 256 + threadIdx.x) * 8;
    float4 a = *(const float4*)(X + i);
    float4 b = *(const float4*)(X + i + 4);
    float v[8] = {a.x, a.y, a.z, a.w, b.x, b.y, b.z, b.w};
    __nv_bfloat16 h[8], l[8];
    #pragma unroll
    for (int j = 0; j < 8; j++) split1(v[j], h[j], l[j]);
    *(uint4*)(hi + i) = *(const uint4*)h;
    *(uint4*)(lo + i) = *(const uint4*)l;
}

// W (K,N) fp32 -> W^T (N,K) hi/lo bf16, tiled transpose.
__global__ __launch_bounds__(256) void splitT_k(const float* __restrict__ W,
                                                __nv_bfloat16* __restrict__ hiT,
                                                __nv_bfloat16* __restrict__ loT,
                                                int K, int N)
{
    __shared__ float sm[32][33];
    const int n0 = blockIdx.x * 32, k0 = blockIdx.y * 32;
    const int tx = threadIdx.x & 31, ty = threadIdx.x >> 5;   // 32 x 8
    #pragma unroll
    for (int i = 0; i < 4; i++)
        sm[ty + i * 8][tx] = W[(size_t)(k0 + ty + i * 8) * N + n0 + tx];
    __syncthreads();
    #pragma unroll
    for (int i = 0; i < 4; i++) {
        int n = n0 + ty + i * 8;
        float v = sm[tx][ty + i * 8];
        __nv_bfloat16 h, l;
        split1(v, h, l);
        hiT[(size_t)n * K + k0 + tx] = h;
        loT[(size_t)n * K + k0 + tx] = l;
    }
}

// ================= HMMA split-bf16 GEMM, 128x64 tile, 2-stage, 3 CTAs/SM =======
// C(M,N) = (ah+al)(M,K) @ (bh+bl)^T, b stored (N,K) K-contiguous.
// CTA tile 128x64, 8 warps (4x2 of 32x32 warp tiles), k-block 32.
// __launch_bounds__(256,3): regs<=83 -> 3 CTAs/SM = 6 warps/SMSP
// (occupancy experiment: is the 46% tensor ceiling warp-starvation?)
// Stage: Ah@0 Al@10240 Bh@20480 Bl@25600; stage size 30720; 2 stages = 61440 B.
#define HG_STAGE 30720
#define HG_SMEM  (2 * HG_STAGE)

template<bool BIAS>
__global__ __launch_bounds__(256, 3) void hgemm(const __nv_bfloat16* __restrict__ ah,
                                                const __nv_bfloat16* __restrict__ al,
                                                const __nv_bfloat16* __restrict__ bh,
                                                const __nv_bfloat16* __restrict__ bl,
                                                const float* __restrict__ bias,
                                                float* __restrict__ C,
                                                int M, int N, int K)
{
    extern __shared__ char smraw[];
    const uint32_t sb = s2u(smraw);
    const int t = threadIdx.x, warp = t >> 5, lane = t & 31;
    const int wm = warp >> 1, wn = warp & 1;          // 4 x 2 warp grid
    const int bm = blockIdx.y << 7, bn = blockIdx.x << 6;

    // cp.async mapping: 6 chunks of 16B per thread per k-block
    uint32_t s_dst[6];
    const __nv_bfloat16* s_src[6];
    #pragma unroll
    for (int i = 0; i < 6; i++) {
        int c = t + (i << 8);
        if (c < 1024) {
            int hi = (c < 512);
            int cc = c & 511, row = cc >> 2, ch = cc & 3;
            s_src[i] = (hi ? ah : al) + (size_t)(bm + row) * K + (ch << 3);
            s_dst[i] = (hi ? 0u : 10240u) + row * 80 + (ch << 4);
        } else {
            int d = c - 1024;
            int hi = (d < 256);
            int cc = d & 255, row = cc >> 2, ch = cc & 3;
            s_src[i] = (hi ? bh : bl) + (size_t)(bn + row) * K + (ch << 3);
            s_dst[i] = 20480u + (hi ? 0u : 5120u) + row * 80 + (ch << 4);
        }
    }

    const int g = lane >> 3, r = lane & 7;
    const uint32_t a_off = (uint32_t)((((g & 1) << 3) + r) * 80 + ((g >> 1) << 4));
    const uint32_t b_off = (uint32_t)((((g >> 1) << 3) + r) * 80 + ((g & 1) << 4));
    const uint32_t aw = (uint32_t)(wm * 32) * 80;
    const uint32_t bw = (uint32_t)(wn * 32) * 80;

    float acc[2][4][4] = {};

    const int nb = K >> 5;
    // prologue: block 0 -> stage 0
    #pragma unroll
    for (int i = 0; i < 6; i++) cp16(sb + s_dst[i], s_src[i]);
    cp_commit();

    uint32_t bufo = 0;
    for (int blk = 0; blk < nb; blk++) {
        cp_wait0();        // stage blk resident
        __syncthreads();   // data visible; prev compute done -> other stage free
        if (blk + 1 < nb) {
            const int k0 = (blk + 1) << 5;
            const uint32_t nxt = bufo ^ (uint32_t)HG_STAGE;
            #pragma unroll
            for (int i = 0; i < 6; i++) cp16(sb + nxt + s_dst[i], s_src[i] + k0);
            cp_commit();
        }

        const uint32_t sA = sb + bufo;
        const uint32_t sB = sb + bufo + 20480u;
        #pragma unroll
        for (int ks = 0; ks < 2; ks++) {
            const uint32_t kso = (uint32_t)(ks << 5);
            uint32_t fah[2][4], fal[2][4];
            #pragma unroll
            for (int ms = 0; ms < 2; ms++) {
                ldsm4(fah[ms], sA +          aw + (uint32_t)(ms * 16) * 80 + kso + a_off);
                ldsm4(fal[ms], sA + 10240u + aw + (uint32_t)(ms * 16) * 80 + kso + a_off);
            }
            #pragma unroll
            for (int ns = 0; ns < 2; ns++) {
                uint32_t fbh[4], fbl[4];
                ldsm4(fbh, sB +         bw + (uint32_t)(ns * 16) * 80 + kso + b_off);
                ldsm4(fbl, sB + 5120u + bw + (uint32_t)(ns * 16) * 80 + kso + b_off);
                #pragma unroll
                for (int ms = 0; ms < 2; ms++)
                    #pragma unroll
                    for (int j = 0; j < 2; j++) {
                        float* a4 = acc[ms][ns * 2 + j];
                        mma16816(a4, fah[ms], fbh + j * 2);
                        mma16816(a4, fah[ms], fbl + j * 2);
                        mma16816(a4, fal[ms], fbh + j * 2);
                    }
            }
        }
        // no trailing barrier; next iter's barrier protects stage reuse
        bufo ^= (uint32_t)HG_STAGE;
    }

    // epilogue
    const int mb = bm + wm * 32;
    const int nbase = bn + wn * 32;
    #pragma unroll
    for (int ms = 0; ms < 2; ms++) {
        const int m0 = mb + ms * 16 + (lane >> 2);
        #pragma unroll
        for (int ng = 0; ng < 4; ng++) {
            const int col = nbase + ng * 8 + ((lane & 3) << 1);
            float bx = 0.f, by = 0.f;
            if (BIAS) { bx = bias[col]; by = bias[col + 1]; }
            float2 v0 = make_float2(acc[ms][ng][0] + bx, acc[ms][ng][1] + by);
            float2 v1 = make_float2(acc[ms][ng][2] + bx, acc[ms][ng][3] + by);
            *(float2*)(C + (size_t)m0 * N + col)       = v0;
            *(float2*)(C + (size_t)(m0 + 8) * N + col) = v1;
        }
    }
}

// ---------------- partial gram: for (h,r), P = k_rh^T k_rh ----------------
__global__ __launch_bounds__(256) void gram_partial_k()
{
    const int h = blockIdx.x, r = blockIdx.y;
    __shared__ float ks[32][64];
    const int t = threadIdx.x, ty = t >> 4, tx = t & 15;
    const float* kb = g_k + (size_t)r * N_ * D_ + h * HD_;
    float acc[4][4] = {};
    for (int c = 0; c < N_; c += 32) {
        #pragma unroll
        for (int i = 0; i < 8; i++) {
            int idx = t + i * 256;
            int nn = idx >> 6, ii = idx & 63;
            ks[nn][ii] = kb[(size_t)(c + nn) * D_ + ii];
        }
        __syncthreads();
        #pragma unroll
        for (int nn = 0; nn < 32; nn++) {
            float4 a = *(const float4*)&ks[nn][ty * 4];
            float4 b = *(const float4*)&ks[nn][tx * 4];
            float av[4] = {a.x, a.y, a.z, a.w};
            float bv[4] = {b.x, b.y, b.z, b.w};
            #pragma unroll
            for (int i = 0; i < 4; i++)
                #pragma unroll
                for (int j = 0; j < 4; j++)
                    acc[i][j] = fmaf(av[i], bv[j], acc[i][j]);
        }
        __syncthreads();
    }
    float* out = g_Gp + ((size_t)h * R_ + r) * (HD_ * HD_);
    #pragma unroll
    for (int i = 0; i < 4; i++) {
        float4 rr;
        rr.x = acc[i][0] * GSCALE; rr.y = acc[i][1] * GSCALE;
        rr.z = acc[i][2] * GSCALE; rr.w = acc[i][3] * GSCALE;
        *(float4*)&out[(ty * 4 + i) * HD_ + tx * 4] = rr;
    }
}

__global__ __launch_bounds__(256) void gram_reduce_k()
{
    int e = blockIdx.x * 256 + threadIdx.x;
    int h = e / (HD_ * HD_);
    int o = e - h * (HD_ * HD_);
    float s = 0.f;
    #pragma unroll
    for (int r = 0; r < R_; r++)
        s += g_Gp[((size_t)h * R_ + r) * (HD_ * HD_) + o];
    g_G[e] = s;
}

// ---------------- fused per-(b,h): P=q^T v; M=G@P; y=q@M -> bf16 hi/lo ----------
__global__ __launch_bounds__(256) void pmy_k()
{
    const int bh = blockIdx.x;
    const int b = bh / H_, h = bh % H_;
    __shared__ union {
        struct { float qs[32][64]; float vs[32][64]; } s;
        float Gst[64][68];
        float qt[64][68];
    } u;
    __shared__ float Ps[64][64];   // holds P, then M
    const int t = threadIdx.x, ty = t >> 4, tx = t & 15;
    const float* qb = g_qv + (size_t)b * N_ * D2_ + h * HD_;
    const float* vb = qb + D_;

    // phase 1a: P = q^T v over N=256
    float acc[4][4] = {};
    for (int c = 0; c < N_; c += 32) {
        #pragma unroll
        for (int i = 0; i < 8; i++) {
            int idx = t + i * 256;
            int nn = idx >> 6, ii = idx & 63;
            size_t off = (size_t)(c + nn) * D2_ + ii;
            u.s.qs[nn][ii] = qb[off];
            u.s.vs[nn][ii] = vb[off];
        }
        __syncthreads();
        #pragma unroll
        for (int nn = 0; nn < 32; nn++) {
            float4 a = *(const float4*)&u.s.qs[nn][ty * 4];
            float4 b4 = *(const float4*)&u.s.vs[nn][tx * 4];
            float av[4] = {a.x, a.y, a.z, a.w};
            float bv[4] = {b4.x, b4.y, b4.z, b4.w};
            #pragma unroll
            for (int i = 0; i < 4; i++)
                #pragma unroll
                for (int j = 0; j < 4; j++)
                    acc[i][j] = fmaf(av[i], bv[j], acc[i][j]);
        }
        __syncthreads();
    }
    #pragma unroll
    for (int i = 0; i < 4; i++) {
        float4 rr = make_float4(acc[i][0], acc[i][1], acc[i][2], acc[i][3]);
        *(float4*)&Ps[ty * 4 + i][tx * 4] = rr;
    }
    const float* Gb = g_G + (size_t)h * (HD_ * HD_);
    #pragma unroll
    for (int i = 0; i < 16; i++) {
        int idx = t + i * 256;
        int ig = idx >> 6, tg = idx & 63;
        u.Gst[tg][ig] = Gb[idx];
    }
    __syncthreads();

    // phase 1b: M = G @ P
    float m4[4][4] = {};
    #pragma unroll
    for (int tt = 0; tt < 64; tt++) {
        float4 a  = *(const float4*)&u.Gst[tt][ty * 4];
        float4 b4 = *(const float4*)&Ps[tt][tx * 4];
        float av[4] = {a.x, a.y, a.z, a.w};
        float bv[4] = {b4.x, b4.y, b4.z, b4.w};
        #pragma unroll
        for (int i = 0; i < 4; i++)
            #pragma unroll
            for (int j = 0; j < 4; j++)
                m4[i][j] = fmaf(av[i], bv[j], m4[i][j]);
    }
    __syncthreads();
    #pragma unroll
    for (int i = 0; i < 4; i++) {
        float4 rr = make_float4(m4[i][0], m4[i][1], m4[i][2], m4[i][3]);
        *(float4*)&Ps[ty * 4 + i][tx * 4] = rr;   // Ps now holds M[t][hd]
    }
    __syncthreads();

    // phase 2: y = q @ M in 4 chunks of 64 rows; split-write to g_ah/g_al
    const size_t base = (size_t)b * (N_ * D_) + (size_t)h * (N_ * HD_);
    for (int c4 = 0; c4 < 4; c4++) {
        const int n0 = c4 * 64;
        #pragma unroll
        for (int i = 0; i < 16; i++) {
            int idx = t + i * 256;
            int n = idx >> 6, tt = idx & 63;
            u.qt[tt][n] = qb[(size_t)(n0 + n) * D2_ + tt];
        }
        __syncthreads();
        float yacc[4][4] = {};
        #pragma unroll
        for (int tt = 0; tt < 64; tt++) {
            float4 a  = *(const float4*)&u.qt[tt][ty * 4];
            float4 b4 = *(const float4*)&Ps[tt][tx * 4];
            float av[4] = {a.x, a.y, a.z, a.w};
            float bv[4] = {b4.x, b4.y, b4.z, b4.w};
            #pragma unroll
            for (int i = 0; i < 4; i++)
                #pragma unroll
                for (int j = 0; j < 4; j++)
                    yacc[i][j] = fmaf(av[i], bv[j], yacc[i][j]);
        }
        #pragma unroll
        for (int i = 0; i < 4; i++) {
            int n = n0 + ty * 4 + i;
            size_t off = base + (size_t)n * HD_ + tx * 4;
            __nv_bfloat16 hh[4], ll[4];
            #pragma unroll
            for (int j = 0; j < 4; j++) split1(yacc[i][j], hh[j], ll[j]);
            *(uint2*)(g_ah + off) = *(const uint2*)hh;
            *(uint2*)(g_al + off) = *(const uint2*)ll;
        }
        __syncthreads();
    }
}

// ---------------- layernorm; output either f32 (final) or bf16 hi/lo ----------------
template<bool TO_BF16>
__global__ __launch_bounds__(256) void ln_k(const float* __restrict__ X,
                                            const float* __restrict__ gamma,
                                            const float* __restrict__ beta,
                                            float* __restrict__ out)
{
    const int row = blockIdx.x;
    const int t = threadIdx.x;
    __shared__ float sx[768];
    __shared__ float wsum[8];
    __shared__ float wsq[8];
    const float* x = X + (size_t)row * D_;
    float s = 0.f;
    #pragma unroll
    for (int i = 0; i < 3; i++) {
        float v = x[t + i * 256];
        sx[t + i * 256] = v;
        s += v;
    }
    #pragma unroll
    for (int o = 16; o; o >>= 1) s += __shfl_xor_sync(0xffffffffu, s, o);
    if ((t & 31) == 0) wsum[t >> 5] = s;
    __syncthreads();
    float tot = 0.f;
    #pragma unroll
    for (int w = 0; w < 8; w++) tot += wsum[w];
    const float mu = tot * (1.0f / 768.0f);
    float vs = 0.f;
    #pragma unroll
    for (int i = 0; i < 3; i++) {
        float d = sx[t + i * 256] - mu;
        vs += d * d;
    }
    #pragma unroll
    for (int o = 16; o; o >>= 1) vs += __shfl_xor_sync(0xffffffffu, vs, o);
    if ((t & 31) == 0) wsq[t >> 5] = vs;
    __syncthreads();
    float tot2 = 0.f;
    #pragma unroll
    for (int w = 0; w < 8; w++) tot2 += wsq[w];
    const float rstd = rsqrtf(tot2 * (1.0f / 768.0f) + EPS_);
    #pragma unroll
    for (int i = 0; i < 3; i++) {
        int c = t + i * 256;
        float v = (sx[c] - mu) * rstd * gamma[c] + beta[c];
        if (TO_BF16) {
            __nv_bfloat16 h, l;
            split1(v, h, l);
            g_ah[(size_t)row * D_ + c] = h;
            g_al[(size_t)row * D_ + c] = l;
        } else {
            out[(size_t)row * D_ + c] = v;
        }
    }
}

// ---------------- host orchestration (branched graph: prologue || qv0) ----------
extern "C" void kernel_launch(void* const* d_in, const int* in_sizes, int n_in,
                              void* d_out, int out_size)
{
    const float* x     = (const float*)d_in[0];
    const float* ref   = (const float*)d_in[1];
    const float* Wqv   = (const float*)d_in[2];
    const float* Wk    = (const float*)d_in[3];
    const float* Wproj = (const float*)d_in[4];
    const float* bproj = (const float*)d_in[5];
    const float* gamma = (const float*)d_in[6];
    const float* beta  = (const float*)d_in[7];
    float* out = (float*)d_out;

    cudaFuncSetAttribute(hgemm<false>, cudaFuncAttributeMaxDynamicSharedMemorySize, HG_SMEM);
    cudaFuncSetAttribute(hgemm<true>,  cudaFuncAttributeMaxDynamicSharedMemorySize, HG_SMEM);

    float *pk, *pqv, *ppr;
    cudaGetSymbolAddress((void**)&pk,  g_k);
    cudaGetSymbolAddress((void**)&pqv, g_qv);
    cudaGetSymbolAddress((void**)&ppr, g_pr);
    __nv_bfloat16 *pah, *pal, *prh, *prl, *pwqh, *pwql, *pwkh, *pwkl, *pwph, *pwpl;
    cudaGetSymbolAddress((void**)&pah,  g_ah);
    cudaGetSymbolAddress((void**)&pal,  g_al);
    cudaGetSymbolAddress((void**)&prh,  g_rh);
    cudaGetSymbolAddress((void**)&prl,  g_rl);
    cudaGetSymbolAddress((void**)&pwqh, g_wqh);
    cudaGetSymbolAddress((void**)&pwql, g_wql);
    cudaGetSymbolAddress((void**)&pwkh, g_wkh);
    cudaGetSymbolAddress((void**)&pwkl, g_wkl);
    cudaGetSymbolAddress((void**)&pwph, g_wph);
    cudaGetSymbolAddress((void**)&pwpl, g_wpl);

    // side stream + events (host objects only; no device allocation).
    cudaStream_t sB;
    cudaStreamCreateWithFlags(&sB, cudaStreamNonBlocking);
    cudaEvent_t evF, evJ;
    cudaEventCreateWithFlags(&evF, cudaEventDisableTiming);
    cudaEventCreateWithFlags(&evJ, cudaEventDisableTiming);

    // fork: side stream depends on the start of the captured stream
    cudaEventRecord(evF, 0);
    cudaStreamWaitEvent(sB, evF, 0);

    // ---- stream B: k/G prologue (touches only g_r*, g_wk*, g_k, g_Gp, g_G, g_wp*) ----
    splitT_k<<<dim3(D_ / 32, D_ / 32), 256, 0, sB>>>(Wk, pwkh, pwkl, D_, D_);
    split_k<<<(R_ * N_ * D_) / 2048, 256, 0, sB>>>(ref, prh, prl);
    hgemm<false><<<dim3(D_ / 64, (R_ * N_) / 128), 256, HG_SMEM, sB>>>(
        prh, prl, pwkh, pwkl, nullptr, pk, R_ * N_, D_, D_);
    gram_partial_k<<<dim3(H_, R_), 256, 0, sB>>>();
    gram_reduce_k<<<(H_ * HD_ * HD_) / 256, 256, 0, sB>>>();
    splitT_k<<<dim3(D_ / 32, D_ / 32), 256, 0, sB>>>(Wproj, pwph, pwpl, D_, D_);
    cudaEventRecord(evJ, sB);

    // ---- default stream: qv chain (touches g_wq*, g_ah/g_al, g_qv) ----
    splitT_k<<<dim3(D2_ / 32, D_ / 32), 256>>>(Wqv, pwqh, pwql, D_, D2_);
    split_k<<<(B_ * N_ * D_) / 2048, 256>>>(x, pah, pal);
    hgemm<false><<<dim3(D2_ / 64, (B_ * N_) / 128), 256, HG_SMEM>>>(
        pah, pal, pwqh, pwql, nullptr, pqv, B_ * N_, D2_, D_);

    // join: pmy needs g_G (B) and g_qv (default); proj needs g_wp* (B)
    cudaStreamWaitEvent((cudaStream_t)0, evJ, 0);

    for (int step = 0; step < 3; step++) {
        // fused P/M/y (writes bf16 hi/lo y into g_ah/g_al)
        pmy_k<<<B_ * H_, 256>>>();

        // proj + bias
        hgemm<true><<<dim3(D_ / 64, (B_ * N_) / 128), 256, HG_SMEM>>>(
            pah, pal, pwph, pwpl, bproj, ppr, B_ * N_, D_, D_);

        // layernorm
        if (step < 2) ln_k<true><<<B_ * N_, 256>>>(ppr, gamma, beta, nullptr);
        else          ln_k<false><<<B_ * N_, 256>>>(ppr, gamma, beta, out);

        // next step's qv
        if (step < 2)
            hgemm<false><<<dim3(D2_ / 64, (B_ * N_) / 128), 256, HG_SMEM>>>(
                pah, pal, pwqh, pwql, nullptr, pqv, B_ * N_, D2_, D_);
    }
}

// round 15
// speedup vs baseline: 1.0273x; 1.0273x over previous
#include <cuda_runtime.h>
#include <cuda_bf16.h>
#include <cstdint>

// Problem constants
#define B_   8
#define N_   256
#define D_   768
#define D2_  1536
#define H_   12
#define HD_  64
#define R_   10
#define EPS_ 1e-5f
#define GSCALE (1.0f / 640.0f)   // SCALE^2 / R
#define GCH   4                  // gram column-chunks (N split)

// ---------------- scratch (device globals; no allocation allowed) ----------------
__device__ float g_k [R_ * N_ * D_];               // ref @ Wk   (2560 x 768)
__device__ float g_Gp[H_ * R_ * GCH * HD_ * HD_];  // per-(h,r,chunk) partial grams
__device__ float g_G [H_ * HD_ * HD_];             // Gbar_h
__device__ float g_qv[B_ * N_ * 2 * D_];           // x @ Wqv    (2048 x 1536)
__device__ float g_pr[B_ * N_ * D_];               // proj output pre-LN

// split-bf16 buffers (hi/lo)
__device__ __nv_bfloat16 g_ah [2048 * 768];   // activations / y
__device__ __nv_bfloat16 g_al [2048 * 768];
__device__ __nv_bfloat16 g_rh [2560 * 768];   // ref split (separate from g_a*)
__device__ __nv_bfloat16 g_rl [2560 * 768];
__device__ __nv_bfloat16 g_wqh[1536 * 768];   // Wqv^T hi  (N,K)
__device__ __nv_bfloat16 g_wql[1536 * 768];
__device__ __nv_bfloat16 g_wkh[ 768 * 768];   // Wk^T
__device__ __nv_bfloat16 g_wkl[ 768 * 768];
__device__ __nv_bfloat16 g_wph[ 768 * 768];   // Wproj^T
__device__ __nv_bfloat16 g_wpl[ 768 * 768];

// ================= low-level helpers (sm_80-era PTX only) =================
__device__ __forceinline__ uint32_t s2u(const void* p) {
    uint32_t a;
    asm("{ .reg .u64 t; cvta.to.shared.u64 t, %1; cvt.u32.u64 %0, t; }" : "=r"(a) : "l"(p));
    return a;
}
__device__ __forceinline__ void cp16(uint32_t sm, const void* gp) {
    asm volatile("cp.async.cg.shared.global [%0], [%1], 16;" :: "r"(sm), "l"(gp));
}
__device__ __forceinline__ void cp_commit() { asm volatile("cp.async.commit_group;"); }
__device__ __forceinline__ void cp_wait0()  { asm volatile("cp.async.wait_group 0;"); }
__device__ __forceinline__ void cp_wait1()  { asm volatile("cp.async.wait_group 1;"); }

__device__ __forceinline__ void ldsm4(uint32_t* r, uint32_t a) {
    asm volatile("ldmatrix.sync.aligned.m8n8.x4.shared.b16 {%0,%1,%2,%3}, [%4];"
                 : "=r"(r[0]), "=r"(r[1]), "=r"(r[2]), "=r"(r[3]) : "r"(a));
}
__device__ __forceinline__ void mma16816(float* c, const uint32_t* a, const uint32_t* b) {
    asm volatile("mma.sync.aligned.m16n8k16.row.col.f32.bf16.bf16.f32 "
                 "{%0,%1,%2,%3}, {%4,%5,%6,%7}, {%8,%9}, {%0,%1,%2,%3};"
                 : "+f"(c[0]), "+f"(c[1]), "+f"(c[2]), "+f"(c[3])
                 : "r"(a[0]), "r"(a[1]), "r"(a[2]), "r"(a[3]), "r"(b[0]), "r"(b[1]));
}
__device__ __forceinline__ void split1(float v, __nv_bfloat16& h, __nv_bfloat16& l) {
    h = __float2bfloat16(v);
    l = __float2bfloat16(v - __bfloat162float(h));
}

// ================= split kernels =================
__global__ __launch_bounds__(256) void split_k(const float* __restrict__ X,
                                               __nv_bfloat16* __restrict__ hi,
                                               __nv_bfloat16* __restrict__ lo)
{
    size_t i = ((size_t)blockIdx.x * 256 + threadIdx.x) * 8;
    float4 a = *(const float4*)(X + i);
    float4 b = *(const float4*)(X + i + 4);
    float v[8] = {a.x, a.y, a.z, a.w, b.x, b.y, b.z, b.w};
    __nv_bfloat16 h[8], l[8];
    #pragma unroll
    for (int j = 0; j < 8; j++) split1(v[j], h[j], l[j]);
    *(uint4*)(hi + i) = *(const uint4*)h;
    *(uint4*)(lo + i) = *(const uint4*)l;
}

// W (K,N) fp32 -> W^T (N,K) hi/lo bf16, tiled transpose.
__global__ __launch_bounds__(256) void splitT_k(const float* __restrict__ W,
                                                __nv_bfloat16* __restrict__ hiT,
                                                __nv_bfloat16* __restrict__ loT,
                                                int K, int N)
{
    __shared__ float sm[32][33];
    const int n0 = blockIdx.x * 32, k0 = blockIdx.y * 32;
    const int tx = threadIdx.x & 31, ty = threadIdx.x >> 5;   // 32 x 8
    #pragma unroll
    for (int i = 0; i < 4; i++)
        sm[ty + i * 8][tx] = W[(size_t)(k0 + ty + i * 8) * N + n0 + tx];
    __syncthreads();
    #pragma unroll
    for (int i = 0; i < 4; i++) {
        int n = n0 + ty + i * 8;
        float v = sm[tx][ty + i * 8];
        __nv_bfloat16 h, l;
        split1(v, h, l);
        hiT[(size_t)n * K + k0 + tx] = h;
        loT[(size_t)n * K + k0 + tx] = l;
    }
}

// ================= HMMA split-bf16 GEMM (R13-proven: 3-stage, NT-templated) ======
template<int NT, bool BIAS>
__global__ __launch_bounds__(256, 2) void hgemm(const __nv_bfloat16* __restrict__ ah,
                                                const __nv_bfloat16* __restrict__ al,
                                                const __nv_bfloat16* __restrict__ bh,
                                                const __nv_bfloat16* __restrict__ bl,
                                                const float* __restrict__ bias,
                                                float* __restrict__ C,
                                                int M, int N, int K)
{
    constexpr int BT    = NT * 80;            // bytes per B tile
    constexpr int STAGE = 20480 + 2 * BT;
    constexpr int NCH   = 4 + NT / 32;        // 16B chunks per thread per k-block
    constexpr int NG    = NT / 16;            // n8-groups per warp
    constexpr int NS    = NT / 32;            // 16-col B groups per warp

    extern __shared__ char smraw[];
    const uint32_t sb = s2u(smraw);
    const int t = threadIdx.x, warp = t >> 5, lane = t & 31;
    const int wm = warp >> 1, wn = warp & 1;          // 4 x 2 warp grid
    const int bm = blockIdx.y << 7, bn = blockIdx.x * NT;

    uint32_t s_dst[NCH];
    const __nv_bfloat16* s_src[NCH];
    #pragma unroll
    for (int i = 0; i < NCH; i++) {
        int c = t + (i << 8);
        if (c < 1024) {
            int hi = (c < 512);
            int cc = c & 511, row = cc >> 2, ch = cc & 3;
            s_src[i] = (hi ? ah : al) + (size_t)(bm + row) * K + (ch << 3);
            s_dst[i] = (hi ? 0u : 10240u) + row * 80 + (ch << 4);
        } else {
            int d = c - 1024;
            int hi = (d < 4 * NT);
            int cc = hi ? d : d - 4 * NT;
            int row = cc >> 2, ch = cc & 3;
            s_src[i] = (hi ? bh : bl) + (size_t)(bn + row) * K + (ch << 3);
            s_dst[i] = 20480u + (hi ? 0u : (uint32_t)BT) + row * 80 + (ch << 4);
        }
    }

    const int g = lane >> 3, r = lane & 7;
    const uint32_t a_off = (uint32_t)((((g & 1) << 3) + r) * 80 + ((g >> 1) << 4));
    const uint32_t b_off = (uint32_t)((((g >> 1) << 3) + r) * 80 + ((g & 1) << 4));
    const uint32_t aw = (uint32_t)(wm * 32) * 80;
    const uint32_t bw = (uint32_t)(wn * (NT / 2)) * 80;

    float acc[2][NG][4] = {};

    const int nb = K >> 5;
    #pragma unroll
    for (int i = 0; i < NCH; i++) cp16(sb + s_dst[i], s_src[i]);
    cp_commit();
    #pragma unroll
    for (int i = 0; i < NCH; i++) cp16(sb + (uint32_t)STAGE + s_dst[i], s_src[i] + 32);
    cp_commit();

    uint32_t off_c = 0, off_1 = (uint32_t)STAGE, off_2 = 2u * (uint32_t)STAGE;
    for (int blk = 0; blk < nb; blk++) {
        if (blk == nb - 1) cp_wait0(); else cp_wait1();
        __syncthreads();
        if (blk + 2 < nb) {
            const int k0 = (blk + 2) << 5;
            #pragma unroll
            for (int i = 0; i < NCH; i++) cp16(sb + off_2 + s_dst[i], s_src[i] + k0);
            cp_commit();
        }

        const uint32_t sA = sb + off_c;
        const uint32_t sB = sb + off_c + 20480u;
        #pragma unroll
        for (int ks = 0; ks < 2; ks++) {
            const uint32_t kso = (uint32_t)(ks << 5);
            uint32_t fah[2][4], fal[2][4], fbh[NS][4], fbl[NS][4];
            #pragma unroll
            for (int ms = 0; ms < 2; ms++) {
                ldsm4(fah[ms], sA +          aw + (uint32_t)(ms * 16) * 80 + kso + a_off);
                ldsm4(fal[ms], sA + 10240u + aw + (uint32_t)(ms * 16) * 80 + kso + a_off);
            }
            #pragma unroll
            for (int ns = 0; ns < NS; ns++) {
                ldsm4(fbh[ns], sB +               bw + (uint32_t)(ns * 16) * 80 + kso + b_off);
                ldsm4(fbl[ns], sB + (uint32_t)BT + bw + (uint32_t)(ns * 16) * 80 + kso + b_off);
            }
            #pragma unroll
            for (int ns = 0; ns < NS; ns++)
                #pragma unroll
                for (int ms = 0; ms < 2; ms++)
                    #pragma unroll
                    for (int j = 0; j < 2; j++)
                        mma16816(acc[ms][ns * 2 + j], fah[ms], fbh[ns] + j * 2);
            #pragma unroll
            for (int ns = 0; ns < NS; ns++)
                #pragma unroll
                for (int ms = 0; ms < 2; ms++)
                    #pragma unroll
                    for (int j = 0; j < 2; j++)
                        mma16816(acc[ms][ns * 2 + j], fah[ms], fbl[ns] + j * 2);
            #pragma unroll
            for (int ns = 0; ns < NS; ns++)
                #pragma unroll
                for (int ms = 0; ms < 2; ms++)
                    #pragma unroll
                    for (int j = 0; j < 2; j++)
                        mma16816(acc[ms][ns * 2 + j], fal[ms], fbh[ns] + j * 2);
        }
        uint32_t tmp = off_c; off_c = off_1; off_1 = off_2; off_2 = tmp;
    }

    const int mb = bm + wm * 32;
    const int nbase = bn + wn * (NT / 2);
    #pragma unroll
    for (int ms = 0; ms < 2; ms++) {
        const int m0 = mb + ms * 16 + (lane >> 2);
        #pragma unroll
        for (int ng = 0; ng < NG; ng++) {
            const int col = nbase + ng * 8 + ((lane & 3) << 1);
            float bx = 0.f, by = 0.f;
            if (BIAS) { bx = bias[col]; by = bias[col + 1]; }
            float2 v0 = make_float2(acc[ms][ng][0] + bx, acc[ms][ng][1] + by);
            float2 v1 = make_float2(acc[ms][ng][2] + bx, acc[ms][ng][3] + by);
            *(float2*)(C + (size_t)m0 * N + col)       = v0;
            *(float2*)(C + (size_t)(m0 + 8) * N + col) = v1;
        }
    }
}

#define HG64_SMEM (3 * (20480 + 2 * 64 * 80))
#define HG96_SMEM (3 * (20480 + 2 * 96 * 80))

// ---------------- partial gram, 4-way N-chunked: grid (H, R*GCH) ----------------
// block (h, r*GCH + chunk) computes k_rh[chunk*64 .. +64)^T @ same -> partial
__global__ __launch_bounds__(256) void gram_partial_k()
{
    const int h = blockIdx.x;
    const int rc = blockIdx.y;
    const int r = rc / GCH, chunk = rc % GCH;
    __shared__ float ks[32][64];
    const int t = threadIdx.x, ty = t >> 4, tx = t & 15;
    const float* kb = g_k + (size_t)r * N_ * D_ + h * HD_;
    const int c0 = chunk * (N_ / GCH);
    float acc[4][4] = {};
    for (int c = c0; c < c0 + N_ / GCH; c += 32) {
        #pragma unroll
        for (int i = 0; i < 8; i++) {
            int idx = t + i * 256;
            int nn = idx >> 6, ii = idx & 63;
            ks[nn][ii] = kb[(size_t)(c + nn) * D_ + ii];
        }
        __syncthreads();
        #pragma unroll
        for (int nn = 0; nn < 32; nn++) {
            float4 a = *(const float4*)&ks[nn][ty * 4];
            float4 b = *(const float4*)&ks[nn][tx * 4];
            float av[4] = {a.x, a.y, a.z, a.w};
            float bv[4] = {b.x, b.y, b.z, b.w};
            #pragma unroll
            for (int i = 0; i < 4; i++)
                #pragma unroll
                for (int j = 0; j < 4; j++)
                    acc[i][j] = fmaf(av[i], bv[j], acc[i][j]);
        }
        __syncthreads();
    }
    float* out = g_Gp + ((size_t)h * (R_ * GCH) + rc) * (HD_ * HD_);
    #pragma unroll
    for (int i = 0; i < 4; i++) {
        float4 rr;
        rr.x = acc[i][0] * GSCALE; rr.y = acc[i][1] * GSCALE;
        rr.z = acc[i][2] * GSCALE; rr.w = acc[i][3] * GSCALE;
        *(float4*)&out[(ty * 4 + i) * HD_ + tx * 4] = rr;
    }
}

__global__ __launch_bounds__(256) void gram_reduce_k()
{
    int e = blockIdx.x * 256 + threadIdx.x;
    int h = e / (HD_ * HD_);
    int o = e - h * (HD_ * HD_);
    float s = 0.f;
    #pragma unroll
    for (int rc = 0; rc < R_ * GCH; rc++)
        s += g_Gp[((size_t)h * (R_ * GCH) + rc) * (HD_ * HD_) + o];
    g_G[e] = s;
}

// ---------------- fused per-(b,h): P=q^T v; M=G@P; y=q@M -> bf16 hi/lo ----------
__global__ __launch_bounds__(256) void pmy_k()
{
    const int bh = blockIdx.x;
    const int b = bh / H_, h = bh % H_;
    __shared__ union {
        struct { float qs[32][64]; float vs[32][64]; } s;
        float Gst[64][68];
        float qt[64][68];
    } u;
    __shared__ float Ps[64][64];   // holds P, then M
    const int t = threadIdx.x, ty = t >> 4, tx = t & 15;
    const float* qb = g_qv + (size_t)b * N_ * D2_ + h * HD_;
    const float* vb = qb + D_;

    float acc[4][4] = {};
    for (int c = 0; c < N_; c += 32) {
        #pragma unroll
        for (int i = 0; i < 8; i++) {
            int idx = t + i * 256;
            int nn = idx >> 6, ii = idx & 63;
            size_t off = (size_t)(c + nn) * D2_ + ii;
            u.s.qs[nn][ii] = qb[off];
            u.s.vs[nn][ii] = vb[off];
        }
        __syncthreads();
        #pragma unroll
        for (int nn = 0; nn < 32; nn++) {
            float4 a = *(const float4*)&u.s.qs[nn][ty * 4];
            float4 b4 = *(const float4*)&u.s.vs[nn][tx * 4];
            float av[4] = {a.x, a.y, a.z, a.w};
            float bv[4] = {b4.x, b4.y, b4.z, b4.w};
            #pragma unroll
            for (int i = 0; i < 4; i++)
                #pragma unroll
                for (int j = 0; j < 4; j++)
                    acc[i][j] = fmaf(av[i], bv[j], acc[i][j]);
        }
        __syncthreads();
    }
    #pragma unroll
    for (int i = 0; i < 4; i++) {
        float4 rr = make_float4(acc[i][0], acc[i][1], acc[i][2], acc[i][3]);
        *(float4*)&Ps[ty * 4 + i][tx * 4] = rr;
    }
    const float* Gb = g_G + (size_t)h * (HD_ * HD_);
    #pragma unroll
    for (int i = 0; i < 16; i++) {
        int idx = t + i * 256;
        int ig = idx >> 6, tg = idx & 63;
        u.Gst[tg][ig] = Gb[idx];
    }
    __syncthreads();

    float m4[4][4] = {};
    #pragma unroll
    for (int tt = 0; tt < 64; tt++) {
        float4 a  = *(const float4*)&u.Gst[tt][ty * 4];
        float4 b4 = *(const float4*)&Ps[tt][tx * 4];
        float av[4] = {a.x, a.y, a.z, a.w};
        float bv[4] = {b4.x, b4.y, b4.z, b4.w};
        #pragma unroll
        for (int i = 0; i < 4; i++)
            #pragma unroll
            for (int j = 0; j < 4; j++)
                m4[i][j] = fmaf(av[i], bv[j], m4[i][j]);
    }
    __syncthreads();
    #pragma unroll
    for (int i = 0; i < 4; i++) {
        float4 rr = make_float4(m4[i][0], m4[i][1], m4[i][2], m4[i][3]);
        *(float4*)&Ps[ty * 4 + i][tx * 4] = rr;   // Ps now holds M[t][hd]
    }
    __syncthreads();

    const size_t base = (size_t)b * (N_ * D_) + (size_t)h * (N_ * HD_);
    for (int c4 = 0; c4 < 4; c4++) {
        const int n0 = c4 * 64;
        #pragma unroll
        for (int i = 0; i < 16; i++) {
            int idx = t + i * 256;
            int n = idx >> 6, tt = idx & 63;
            u.qt[tt][n] = qb[(size_t)(n0 + n) * D2_ + tt];
        }
        __syncthreads();
        float yacc[4][4] = {};
        #pragma unroll
        for (int tt = 0; tt < 64; tt++) {
            float4 a  = *(const float4*)&u.qt[tt][ty * 4];
            float4 b4 = *(const float4*)&Ps[tt][tx * 4];
            float av[4] = {a.x, a.y, a.z, a.w};
            float bv[4] = {b4.x, b4.y, b4.z, b4.w};
            #pragma unroll
            for (int i = 0; i < 4; i++)
                #pragma unroll
                for (int j = 0; j < 4; j++)
                    yacc[i][j] = fmaf(av[i], bv[j], yacc[i][j]);
        }
        #pragma unroll
        for (int i = 0; i < 4; i++) {
            int n = n0 + ty * 4 + i;
            size_t off = base + (size_t)n * HD_ + tx * 4;
            __nv_bfloat16 hh[4], ll[4];
            #pragma unroll
            for (int j = 0; j < 4; j++) split1(yacc[i][j], hh[j], ll[j]);
            *(uint2*)(g_ah + off) = *(const uint2*)hh;
            *(uint2*)(g_al + off) = *(const uint2*)ll;
        }
        __syncthreads();
    }
}

// ---------------- layernorm; output either f32 (final) or bf16 hi/lo ----------------
template<bool TO_BF16>
__global__ __launch_bounds__(256) void ln_k(const float* __restrict__ X,
                                            const float* __restrict__ gamma,
                                            const float* __restrict__ beta,
                                            float* __restrict__ out)
{
    const int row = blockIdx.x;
    const int t = threadIdx.x;
    __shared__ float sx[768];
    __shared__ float wsum[8];
    __shared__ float wsq[8];
    const float* x = X + (size_t)row * D_;
    float s = 0.f;
    #pragma unroll
    for (int i = 0; i < 3; i++) {
        float v = x[t + i * 256];
        sx[t + i * 256] = v;
        s += v;
    }
    #pragma unroll
    for (int o = 16; o; o >>= 1) s += __shfl_xor_sync(0xffffffffu, s, o);
    if ((t & 31) == 0) wsum[t >> 5] = s;
    __syncthreads();
    float tot = 0.f;
    #pragma unroll
    for (int w = 0; w < 8; w++) tot += wsum[w];
    const float mu = tot * (1.0f / 768.0f);
    float vs = 0.f;
    #pragma unroll
    for (int i = 0; i < 3; i++) {
        float d = sx[t + i * 256] - mu;
        vs += d * d;
    }
    #pragma unroll
    for (int o = 16; o; o >>= 1) vs += __shfl_xor_sync(0xffffffffu, vs, o);
    if ((t & 31) == 0) wsq[t >> 5] = vs;
    __syncthreads();
    float tot2 = 0.f;
    #pragma unroll
    for (int w = 0; w < 8; w++) tot2 += wsq[w];
    const float rstd = rsqrtf(tot2 * (1.0f / 768.0f) + EPS_);
    #pragma unroll
    for (int i = 0; i < 3; i++) {
        int c = t + i * 256;
        float v = (sx[c] - mu) * rstd * gamma[c] + beta[c];
        if (TO_BF16) {
            __nv_bfloat16 h, l;
            split1(v, h, l);
            g_ah[(size_t)row * D_ + c] = h;
            g_al[(size_t)row * D_ + c] = l;
        } else {
            out[(size_t)row * D_ + c] = v;
        }
    }
}

// ---------------- host orchestration (branched graph: prologue || qv0) ----------
extern "C" void kernel_launch(void* const* d_in, const int* in_sizes, int n_in,
                              void* d_out, int out_size)
{
    const float* x     = (const float*)d_in[0];
    const float* ref   = (const float*)d_in[1];
    const float* Wqv   = (const float*)d_in[2];
    const float* Wk    = (const float*)d_in[3];
    const float* Wproj = (const float*)d_in[4];
    const float* bproj = (const float*)d_in[5];
    const float* gamma = (const float*)d_in[6];
    const float* beta  = (const float*)d_in[7];
    float* out = (float*)d_out;

    cudaFuncSetAttribute(hgemm<64, false>, cudaFuncAttributeMaxDynamicSharedMemorySize, HG64_SMEM);
    cudaFuncSetAttribute(hgemm<64, true>,  cudaFuncAttributeMaxDynamicSharedMemorySize, HG64_SMEM);
    cudaFuncSetAttribute(hgemm<96, false>, cudaFuncAttributeMaxDynamicSharedMemorySize, HG96_SMEM);

    float *pk, *pqv, *ppr;
    cudaGetSymbolAddress((void**)&pk,  g_k);
    cudaGetSymbolAddress((void**)&pqv, g_qv);
    cudaGetSymbolAddress((void**)&ppr, g_pr);
    __nv_bfloat16 *pah, *pal, *prh, *prl, *pwqh, *pwql, *pwkh, *pwkl, *pwph, *pwpl;
    cudaGetSymbolAddress((void**)&pah,  g_ah);
    cudaGetSymbolAddress((void**)&pal,  g_al);
    cudaGetSymbolAddress((void**)&prh,  g_rh);
    cudaGetSymbolAddress((void**)&prl,  g_rl);
    cudaGetSymbolAddress((void**)&pwqh, g_wqh);
    cudaGetSymbolAddress((void**)&pwql, g_wql);
    cudaGetSymbolAddress((void**)&pwkh, g_wkh);
    cudaGetSymbolAddress((void**)&pwkl, g_wkl);
    cudaGetSymbolAddress((void**)&pwph, g_wph);
    cudaGetSymbolAddress((void**)&pwpl, g_wpl);

    // side stream + events (host objects only; no device allocation).
    cudaStream_t sB;
    cudaStreamCreateWithFlags(&sB, cudaStreamNonBlocking);
    cudaEvent_t evF, evJ;
    cudaEventCreateWithFlags(&evF, cudaEventDisableTiming);
    cudaEventCreateWithFlags(&evJ, cudaEventDisableTiming);

    // fork: side stream depends on the start of the captured stream
    cudaEventRecord(evF, 0);
    cudaStreamWaitEvent(sB, evF, 0);

    // ---- stream B: k/G prologue (touches only g_r*, g_wk*, g_k, g_Gp, g_G, g_wp*) ----
    splitT_k<<<dim3(D_ / 32, D_ / 32), 256, 0, sB>>>(Wk, pwkh, pwkl, D_, D_);
    split_k<<<(R_ * N_ * D_) / 2048, 256, 0, sB>>>(ref, prh, prl);
    hgemm<64, false><<<dim3(D_ / 64, (R_ * N_) / 128), 256, HG64_SMEM, sB>>>(
        prh, prl, pwkh, pwkl, nullptr, pk, R_ * N_, D_, D_);
    gram_partial_k<<<dim3(H_, R_ * GCH), 256, 0, sB>>>();
    gram_reduce_k<<<(H_ * HD_ * HD_) / 256, 256, 0, sB>>>();
    splitT_k<<<dim3(D_ / 32, D_ / 32), 256, 0, sB>>>(Wproj, pwph, pwpl, D_, D_);
    cudaEventRecord(evJ, sB);

    // ---- default stream: qv chain (touches g_wq*, g_ah/g_al, g_qv) ----
    splitT_k<<<dim3(D2_ / 32, D_ / 32), 256>>>(Wqv, pwqh, pwql, D_, D2_);
    split_k<<<(B_ * N_ * D_) / 2048, 256>>>(x, pah, pal);
    hgemm<96, false><<<dim3(D2_ / 96, (B_ * N_) / 128), 256, HG96_SMEM>>>(
        pah, pal, pwqh, pwql, nullptr, pqv, B_ * N_, D2_, D_);

    // join: pmy needs g_G (B) and g_qv (default); proj needs g_wp* (B)
    cudaStreamWaitEvent((cudaStream_t)0, evJ, 0);

    for (int step = 0; step < 3; step++) {
        // fused P/M/y (writes bf16 hi/lo y into g_ah/g_al)
        pmy_k<<<B_ * H_, 256>>>();

        // proj + bias
        hgemm<64, true><<<dim3(D_ / 64, (B_ * N_) / 128), 256, HG64_SMEM>>>(
            pah, pal, pwph, pwpl, bproj, ppr, B_ * N_, D_, D_);

        // layernorm
        if (step < 2) ln_k<true><<<B_ * N_, 256>>>(ppr, gamma, beta, nullptr);
        else          ln_k<false><<<B_ * N_, 256>>>(ppr, gamma, beta, out);

        // next step's qv
        if (step < 2)
            hgemm<96, false><<<dim3(D2_ / 96, (B_ * N_) / 128), 256, HG96_SMEM>>>(
                pah, pal, pwqh, pwql, nullptr, pqv, B_ * N_, D2_, D_);
    }
}